// round 1
// baseline (speedup 1.0000x reference)
#include <cuda_runtime.h>
#include <math.h>

// ---------------- problem constants ----------------
#define Hd   256
#define NHd  4
#define HDd  64
#define BAT  8
#define SQI  2048            // image seq len
#define SQT  1024            // text seq len
#define RI   (BAT*SQI)       // 16384 image rows
#define RT   (BAT*SQT)       // 8192 text rows

// ---------------- scratch (device globals, no allocs allowed) ----------------
__device__ float g_qi[(size_t)RI*Hd];
__device__ float g_ki[(size_t)RI*Hd];
__device__ float g_vi[(size_t)RI*Hd];
__device__ float g_qt[(size_t)RT*Hd];
__device__ float g_kt[(size_t)RT*Hd];
__device__ float g_vt[(size_t)RT*Hd];
__device__ float g_ai[(size_t)RI*Hd];   // i2t attn output (pre O-proj)
__device__ float g_at[(size_t)RT*Hd];
__device__ float g_oi[(size_t)RI*Hd];   // i2t O-proj output (pre LN)
__device__ float g_ot[(size_t)RT*Hd];
__device__ float g_S[(size_t)BAT*NHd*SQI*SQT];  // 67,108,864 floats: scores/probs, reused per direction

// ---------------- shared 64x64x16 fp32 GEMM tile body ----------------
// C[m,n] = alpha * sum_k A[m,k]*B[n,k]  (+ bias[n])      (TN form: both K-major)
// C[m,n] = alpha * sum_k A[m,k]*B[k,n]  (+ bias[n])      (NN form)
// Block: 256 threads. Grid: (N/64, M/64). All dims multiples of 64 / 16.

struct TileAcc { float a[4][4]; };

__device__ __forceinline__ void gemm_body(
    const float* __restrict__ A, const float* __restrict__ B,
    const float* __restrict__ bias, float* __restrict__ C,
    int Kdim, int lda, int ldb, int ldc, float alpha, bool b_is_nk /*true: TN*/)
{
    __shared__ float As[16][64];
    __shared__ float Bs[16][64];
    const int tid = threadIdx.x;
    const int m0 = blockIdx.y * 64, n0 = blockIdx.x * 64;
    const int tx = tid & 15, ty = tid >> 4;      // 16 x 16 threads, 4x4 micro-tile

    float acc[4][4];
#pragma unroll
    for (int i = 0; i < 4; i++)
#pragma unroll
        for (int j = 0; j < 4; j++) acc[i][j] = 0.f;

    for (int k0 = 0; k0 < Kdim; k0 += 16) {
        // A tile (64 rows x 16 k), transposed into As[k][m]
        {
            const int m = tid >> 2;
            const int k = (tid & 3) * 4;
            float4 v = *(const float4*)(A + (size_t)(m0 + m) * lda + (k0 + k));
            As[k + 0][m] = v.x; As[k + 1][m] = v.y; As[k + 2][m] = v.z; As[k + 3][m] = v.w;
        }
        if (b_is_nk) {
            // B[n,k] tile, transposed into Bs[k][n]
            const int n = tid >> 2;
            const int k = (tid & 3) * 4;
            float4 v = *(const float4*)(B + (size_t)(n0 + n) * ldb + (k0 + k));
            Bs[k + 0][n] = v.x; Bs[k + 1][n] = v.y; Bs[k + 2][n] = v.z; Bs[k + 3][n] = v.w;
        } else {
            // B[k,n] tile, direct into Bs[k][n]
            const int k = tid >> 4;
            const int n = (tid & 15) * 4;
            float4 v = *(const float4*)(B + (size_t)(k0 + k) * ldb + (n0 + n));
            *(float4*)&Bs[k][n] = v;
        }
        __syncthreads();

#pragma unroll
        for (int kk = 0; kk < 16; kk++) {
            float ar[4], br[4];
            *(float4*)ar = *(const float4*)&As[kk][ty * 4];
            *(float4*)br = *(const float4*)&Bs[kk][tx * 4];
#pragma unroll
            for (int i = 0; i < 4; i++)
#pragma unroll
                for (int j = 0; j < 4; j++) acc[i][j] = fmaf(ar[i], br[j], acc[i][j]);
        }
        __syncthreads();
    }

#pragma unroll
    for (int i = 0; i < 4; i++) {
        const int m = m0 + ty * 4 + i;
#pragma unroll
        for (int j = 0; j < 4; j++) {
            const int n = n0 + tx * 4 + j;
            float v = alpha * acc[i][j];
            if (bias) v += bias[n];
            C[(size_t)m * ldc + n] = v;
        }
    }
}

// Plain GEMM (projections / O-proj): C = A @ W^T + b,  A:[M,256] W:[256,256]
__global__ void k_gemm_tn(const float* __restrict__ A, const float* __restrict__ W,
                          const float* __restrict__ bias, float* __restrict__ C,
                          int Kdim, int lda, int ldb, int ldc)
{
    gemm_body(A, W, bias, C, Kdim, lda, ldb, ldc, 1.0f, true);
}

// Scores: S[b,h,q,k] = 2 * Q[b,q,h,:]·K[b,k,h,:]    grid.z = b*4+h
__global__ void k_scores(const float* __restrict__ Q, const float* __restrict__ Kmat,
                         float* __restrict__ S, int Sq, int Skv)
{
    const int z = blockIdx.z, b = z >> 2, h = z & 3;
    gemm_body(Q + (size_t)b * Sq * Hd + h * HDd,
              Kmat + (size_t)b * Skv * Hd + h * HDd,
              nullptr,
              S + (size_t)z * Sq * Skv,
              HDd, Hd, Hd, Skv, 2.0f /* 1/TEMP */, true);
}

// P @ V:  O[b,q,h,:] = sum_k P[b,h,q,k] * V[b,k,h,:]   grid.z = b*4+h, grid.x = 1 (N=64)
__global__ void k_pv(const float* __restrict__ S, const float* __restrict__ V,
                     float* __restrict__ O, int Sq, int Skv)
{
    const int z = blockIdx.z, b = z >> 2, h = z & 3;
    gemm_body(S + (size_t)z * Sq * Skv,
              V + (size_t)b * Skv * Hd + h * HDd,
              nullptr,
              O + (size_t)b * Sq * Hd + h * HDd,
              Skv, Skv, Hd, Hd, 1.0f, false);
}

// ---------------- softmax over Skv for 4 heads + head-averaged A output ----------------
// grid: (Sq, B), block 256, dyn smem = 4*Skv*4 bytes. Overwrites S with probs in place.
__global__ void k_softmax(float* __restrict__ S, float* __restrict__ A, int Sq, int Skv)
{
    extern __shared__ float sh[];            // [4][Skv]
    __shared__ float red[256];
    __shared__ float inv_sum[4], mx[4];
    const int q = blockIdx.x, b = blockIdx.y, t = threadIdx.x;

#pragma unroll
    for (int h = 0; h < 4; h++) {
        float* row = S + ((size_t)(b * 4 + h) * Sq + q) * (size_t)Skv;
        float lmax = -1e30f;
        for (int k = t; k < Skv; k += 256) {
            float v = row[k];
            sh[h * Skv + k] = v;
            lmax = fmaxf(lmax, v);
        }
        red[t] = lmax; __syncthreads();
        for (int s = 128; s > 0; s >>= 1) {
            if (t < s) red[t] = fmaxf(red[t], red[t + s]);
            __syncthreads();
        }
        if (t == 0) mx[h] = red[0];
        __syncthreads();
        const float m = mx[h];
        float lsum = 0.f;
        for (int k = t; k < Skv; k += 256) {
            float w = __expf(sh[h * Skv + k] - m);
            sh[h * Skv + k] = w;
            lsum += w;
        }
        red[t] = lsum; __syncthreads();
        for (int s = 128; s > 0; s >>= 1) {
            if (t < s) red[t] += red[t + s];
            __syncthreads();
        }
        if (t == 0) inv_sum[h] = 1.f / red[0];
        __syncthreads();
    }

    float* Arow = A + ((size_t)b * Sq + q) * (size_t)Skv;
    for (int k = t; k < Skv; k += 256) {
        float a = 0.f;
#pragma unroll
        for (int h = 0; h < 4; h++) {
            float w = sh[h * Skv + k] * inv_sum[h];
            S[((size_t)(b * 4 + h) * Sq + q) * (size_t)Skv + k] = w;
            a += w;
        }
        Arow[k] = 0.25f * a;
    }
}

// ---------------- relu + LayerNorm (biased var, eps 1e-5) ----------------
// grid: rows, block: 256 (=H), one element per thread
__global__ void k_relu_ln(const float* __restrict__ O, const float* __restrict__ gamma,
                          const float* __restrict__ beta, float* __restrict__ out)
{
    __shared__ float s1[256], s2[256];
    const int row = blockIdx.x, t = threadIdx.x;
    float x = O[(size_t)row * Hd + t];
    x = fmaxf(x, 0.f);
    s1[t] = x; s2[t] = x * x;
    __syncthreads();
    for (int s = 128; s > 0; s >>= 1) {
        if (t < s) { s1[t] += s1[t + s]; s2[t] += s2[t + s]; }
        __syncthreads();
    }
    const float mean = s1[0] * (1.f / Hd);
    const float var  = s2[0] * (1.f / Hd) - mean * mean;
    const float rstd = rsqrtf(var + 1e-5f);
    out[(size_t)row * Hd + t] = (x - mean) * rstd * gamma[t] + beta[t];
}

// ---------------- launch ----------------
extern "C" void kernel_launch(void* const* d_in, const int* in_sizes, int n_in,
                              void* d_out, int out_size)
{
    const float* image   = (const float*)d_in[0];
    const float* text    = (const float*)d_in[1];
    const float* i2t_wq  = (const float*)d_in[2];
    const float* i2t_bq  = (const float*)d_in[3];
    const float* i2t_wk  = (const float*)d_in[4];
    const float* i2t_bk  = (const float*)d_in[5];
    const float* i2t_wv  = (const float*)d_in[6];
    const float* i2t_bv  = (const float*)d_in[7];
    const float* i2t_wo  = (const float*)d_in[8];
    const float* i2t_bo  = (const float*)d_in[9];
    const float* i2t_g   = (const float*)d_in[10];
    const float* i2t_be  = (const float*)d_in[11];
    const float* t2i_wq  = (const float*)d_in[12];
    const float* t2i_bq  = (const float*)d_in[13];
    const float* t2i_wk  = (const float*)d_in[14];
    const float* t2i_bk  = (const float*)d_in[15];
    const float* t2i_wv  = (const float*)d_in[16];
    const float* t2i_bv  = (const float*)d_in[17];
    const float* t2i_wo  = (const float*)d_in[18];
    const float* t2i_bo  = (const float*)d_in[19];
    const float* t2i_g   = (const float*)d_in[20];
    const float* t2i_be  = (const float*)d_in[21];

    float* out = (float*)d_out;
    float* out_i2t_feat = out;                                      // [8,2048,256]
    float* out_t2i_feat = out + (size_t)RI * Hd;                    // [8,1024,256]
    float* out_i2t_A    = out_t2i_feat + (size_t)RT * Hd;           // [8,2048,1024]
    float* out_t2i_A    = out_i2t_A + (size_t)BAT * SQI * SQT;      // [8,1024,2048]

    float *qi, *ki, *vi, *qt, *kt, *vt, *ai, *at, *oi, *ot, *S;
    cudaGetSymbolAddress((void**)&qi, g_qi);
    cudaGetSymbolAddress((void**)&ki, g_ki);
    cudaGetSymbolAddress((void**)&vi, g_vi);
    cudaGetSymbolAddress((void**)&qt, g_qt);
    cudaGetSymbolAddress((void**)&kt, g_kt);
    cudaGetSymbolAddress((void**)&vt, g_vt);
    cudaGetSymbolAddress((void**)&ai, g_ai);
    cudaGetSymbolAddress((void**)&at, g_at);
    cudaGetSymbolAddress((void**)&oi, g_oi);
    cudaGetSymbolAddress((void**)&ot, g_ot);
    cudaGetSymbolAddress((void**)&S,  g_S);

    const dim3 blk(256);

    // ---- projections (Q/K/V for both directions) ----
    k_gemm_tn<<<dim3(Hd/64, RI/64), blk>>>(image, i2t_wq, i2t_bq, qi, Hd, Hd, Hd, Hd);
    k_gemm_tn<<<dim3(Hd/64, RT/64), blk>>>(text,  i2t_wk, i2t_bk, kt, Hd, Hd, Hd, Hd);
    k_gemm_tn<<<dim3(Hd/64, RT/64), blk>>>(text,  i2t_wv, i2t_bv, vt, Hd, Hd, Hd, Hd);
    k_gemm_tn<<<dim3(Hd/64, RT/64), blk>>>(text,  t2i_wq, t2i_bq, qt, Hd, Hd, Hd, Hd);
    k_gemm_tn<<<dim3(Hd/64, RI/64), blk>>>(image, t2i_wk, t2i_bk, ki, Hd, Hd, Hd, Hd);
    k_gemm_tn<<<dim3(Hd/64, RI/64), blk>>>(image, t2i_wv, t2i_bv, vi, Hd, Hd, Hd, Hd);

    // ---- i2t: image queries attend to text ----
    k_scores <<<dim3(SQT/64, SQI/64, BAT*NHd), blk>>>(qi, kt, S, SQI, SQT);
    k_softmax<<<dim3(SQI, BAT), blk, 4*SQT*sizeof(float)>>>(S, out_i2t_A, SQI, SQT);
    k_pv     <<<dim3(1, SQI/64, BAT*NHd), blk>>>(S, vt, ai, SQI, SQT);
    k_gemm_tn<<<dim3(Hd/64, RI/64), blk>>>(ai, i2t_wo, i2t_bo, oi, Hd, Hd, Hd, Hd);
    k_relu_ln<<<RI, blk>>>(oi, i2t_g, i2t_be, out_i2t_feat);

    // ---- t2i: text queries attend to image ----
    k_scores <<<dim3(SQI/64, SQT/64, BAT*NHd), blk>>>(qt, ki, S, SQT, SQI);
    k_softmax<<<dim3(SQT, BAT), blk, 4*SQI*sizeof(float)>>>(S, out_t2i_A, SQT, SQI);
    k_pv     <<<dim3(1, SQT/64, BAT*NHd), blk>>>(S, vi, at, SQT, SQI);
    k_gemm_tn<<<dim3(Hd/64, RT/64), blk>>>(at, t2i_wo, t2i_bo, ot, Hd, Hd, Hd, Hd);
    k_relu_ln<<<RT, blk>>>(ot, t2i_g, t2i_be, out_t2i_feat);
}

// round 7
// speedup vs baseline: 1.6376x; 1.6376x over previous
#include <cuda_runtime.h>
#include <cuda_bf16.h>
#include <cstdint>
#include <math.h>

// ---------------- problem constants ----------------
#define Hd   256
#define NHd  4
#define HDd  64
#define BAT  8
#define SQI  2048
#define SQT  1024
#define RI   (BAT*SQI)       // 16384 image rows
#define RT   (BAT*SQT)       // 8192 text rows

// ---------------- scratch ----------------
__device__ float g_qi[(size_t)RI*Hd];   // packed hi/lo bf16 pairs
__device__ float g_ki[(size_t)RI*Hd];
__device__ float g_vi[(size_t)RI*Hd];   // packed, TRANSPOSED [B*4+hgrp][64][SQI]
__device__ float g_qt[(size_t)RT*Hd];
__device__ float g_kt[(size_t)RT*Hd];
__device__ float g_vt[(size_t)RT*Hd];   // packed, TRANSPOSED
__device__ float g_ai[(size_t)RI*Hd];   // packed attn (pre O-proj)
__device__ float g_at[(size_t)RT*Hd];
__device__ float g_oi[(size_t)RI*Hd];   // fp32 O-proj out
__device__ float g_ot[(size_t)RT*Hd];
__device__ float g_S[(size_t)BAT*NHd*SQI*SQT]; // scores fp32, then packed probs

// ================= helpers =================
__device__ __forceinline__ uint32_t smem_to_u32(const void* p) {
    uint32_t a;
    asm("{ .reg .u64 t; cvta.to.shared.u64 t, %1; cvt.u32.u64 %0, t; }" : "=r"(a) : "l"(p));
    return a;
}
__device__ __forceinline__ void ldm_x4(uint32_t r[4], uint32_t addr) {
    asm volatile("ldmatrix.sync.aligned.m8n8.x4.shared.b16 {%0,%1,%2,%3}, [%4];"
        : "=r"(r[0]), "=r"(r[1]), "=r"(r[2]), "=r"(r[3]) : "r"(addr));
}
__device__ __forceinline__ void mma_bf16(float c[4], const uint32_t a[4],
                                         uint32_t b0, uint32_t b1) {
    asm volatile(
        "mma.sync.aligned.m16n8k16.row.col.f32.bf16.bf16.f32 "
        "{%0,%1,%2,%3}, {%4,%5,%6,%7}, {%8,%9}, {%0,%1,%2,%3};"
        : "+f"(c[0]), "+f"(c[1]), "+f"(c[2]), "+f"(c[3])
        : "r"(a[0]), "r"(a[1]), "r"(a[2]), "r"(a[3]), "r"(b0), "r"(b1));
}

__device__ __forceinline__ void split_f32(uint32_t u, uint32_t& h, uint32_t& l) {
    float x = __uint_as_float(u);
    __nv_bfloat16 hb = __float2bfloat16(x);
    float hf = __bfloat162float(hb);
    __nv_bfloat16 lb = __float2bfloat16(x - hf);
    h = (uint32_t)__bfloat16_as_ushort(hb);
    l = (uint32_t)__bfloat16_as_ushort(lb);
}
__device__ __forceinline__ uint32_t pack_f32(float x) {
    __nv_bfloat16 hb = __float2bfloat16(x);
    float hf = __bfloat162float(hb);
    __nv_bfloat16 lb = __float2bfloat16(x - hf);
    return ((uint32_t)__bfloat16_as_ushort(hb) << 16) | (uint32_t)__bfloat16_as_ushort(lb);
}

// ---------------- smem layout ----------------
// per stage: Ah[128][40]bf16 (10240B), Al (10240B), Bh[64][40] (5120B), Bl (5120B)
#define STG_BYTES 30720
#define OFF_AL 10240
#define OFF_BH 20480
#define OFF_BL 25600
#define SMEM_GEMM (2*STG_BYTES)   // 61440

struct GArgs {
    const uint32_t* A; int lda;
    const uint32_t* B; int ldb;
    const float* bias;
    void* C; int ldc;
    int K; float alpha;
    int m0, n0;
    int tr_ld, tr_rows, tr_col0;
};

template <bool PACKED>
__device__ __forceinline__ void sts4(uint16_t* hi, uint16_t* lo, int idx, uint4 v) {
    uint32_t h0, h1, h2, h3, l0, l1, l2, l3;
    if (PACKED) {
        h0 = v.x >> 16; l0 = v.x & 0xffff;
        h1 = v.y >> 16; l1 = v.y & 0xffff;
        h2 = v.z >> 16; l2 = v.z & 0xffff;
        h3 = v.w >> 16; l3 = v.w & 0xffff;
    } else {
        split_f32(v.x, h0, l0); split_f32(v.y, h1, l1);
        split_f32(v.z, h2, l2); split_f32(v.w, h3, l3);
    }
    *(uint32_t*)(hi + idx)     = h0 | (h1 << 16);
    *(uint32_t*)(hi + idx + 2) = h2 | (h3 << 16);
    *(uint32_t*)(lo + idx)     = l0 | (l1 << 16);
    *(uint32_t*)(lo + idx + 2) = l2 | (l3 << 16);
}

template <bool APACK, bool BPACK, int OMODE, bool BIAS>
__device__ void gemm_mma(GArgs g) {
    extern __shared__ char smem[];
    const uint32_t sbase = smem_to_u32(smem);
    const int tid = threadIdx.x;
    const int lane = tid & 31, wid = tid >> 5;
    const int warpM = wid >> 1, warpN = wid & 1;     // 4 x 2 warps

    float c[2][4][4];
#pragma unroll
    for (int i = 0; i < 2; i++)
#pragma unroll
        for (int j = 0; j < 4; j++)
#pragma unroll
            for (int q = 0; q < 4; q++) c[i][j][q] = 0.f;

    const int S = g.K >> 5;                    // K-chunks of 32
    const int arow = tid >> 1, ak0 = (tid & 1) * 16;
    const int brow = tid >> 2, bk0 = (tid & 3) * 8;

    uint4 areg[4], breg[2];

#define LOADR(s) do { \
        const uint32_t* Ap = g.A + (size_t)(g.m0 + arow) * g.lda + (s) * 32 + ak0; \
        _Pragma("unroll") for (int j = 0; j < 4; j++) areg[j] = *(const uint4*)(Ap + j * 4); \
        const uint32_t* Bp = g.B + (size_t)(g.n0 + brow) * g.ldb + (s) * 32 + bk0; \
        _Pragma("unroll") for (int j = 0; j < 2; j++) breg[j] = *(const uint4*)(Bp + j * 4); \
    } while (0)

#define STS(buf) do { \
        char* p = smem + (buf) * STG_BYTES; \
        uint16_t* Ah = (uint16_t*)p;               uint16_t* Al = (uint16_t*)(p + OFF_AL); \
        uint16_t* Bh = (uint16_t*)(p + OFF_BH);    uint16_t* Bl = (uint16_t*)(p + OFF_BL); \
        _Pragma("unroll") for (int j = 0; j < 4; j++) \
            sts4<APACK>(Ah, Al, arow * 40 + ak0 + j * 4, areg[j]); \
        _Pragma("unroll") for (int j = 0; j < 2; j++) \
            sts4<BPACK>(Bh, Bl, brow * 40 + bk0 + j * 4, breg[j]); \
    } while (0)

    const int sel = lane >> 3, r8 = lane & 7;
    const int rloc = (sel & 1) * 8 + r8;     // row within 16-row tile
    const int cloc = (sel >> 1) * 8;         // col(halves) within 16-k tile

#define COMPUTE(buf) do { \
        uint32_t AhB = sbase + (buf) * STG_BYTES, AlB = AhB + OFF_AL; \
        uint32_t BhB = AhB + OFF_BH,              BlB = AhB + OFF_BL; \
        _Pragma("unroll") for (int kh = 0; kh < 2; kh++) { \
            uint32_t ah[2][4], al[2][4], bh[2][4], bl[2][4]; \
            _Pragma("unroll") for (int i = 0; i < 2; i++) { \
                uint32_t off = (uint32_t)(((warpM * 32 + i * 16 + rloc) * 40 + kh * 16 + cloc) * 2); \
                ldm_x4(ah[i], AhB + off); ldm_x4(al[i], AlB + off); \
            } \
            _Pragma("unroll") for (int pp = 0; pp < 2; pp++) { \
                uint32_t off = (uint32_t)(((warpN * 32 + pp * 16 + rloc) * 40 + kh * 16 + cloc) * 2); \
                ldm_x4(bh[pp], BhB + off); ldm_x4(bl[pp], BlB + off); \
            } \
            _Pragma("unroll") for (int i = 0; i < 2; i++) \
            _Pragma("unroll") for (int j = 0; j < 4; j++) { \
                const int pp = j >> 1, q = j & 1; \
                mma_bf16(c[i][j], ah[i], bh[pp][q], bh[pp][q + 2]); \
                mma_bf16(c[i][j], ah[i], bl[pp][q], bl[pp][q + 2]); \
                mma_bf16(c[i][j], al[i], bh[pp][q], bh[pp][q + 2]); \
            } \
        } \
    } while (0)

    LOADR(0); STS(0);
    __syncthreads();
    for (int s = 0; s < S; ++s) {
        if (s + 1 < S) { LOADR(s + 1); STS((s + 1) & 1); }
        COMPUTE(s & 1);
        __syncthreads();
    }

    // ---------------- epilogue ----------------
    const int gq = lane >> 2, tig = lane & 3;
#pragma unroll
    for (int i = 0; i < 2; i++) {
        const int r0 = g.m0 + warpM * 32 + i * 16 + gq;   // and r0+8
#pragma unroll
        for (int j = 0; j < 4; j++) {
            const int nc = warpN * 32 + j * 8 + tig * 2;   // local col (0..63)
            float v00 = c[i][j][0] * g.alpha, v01 = c[i][j][1] * g.alpha;
            float v10 = c[i][j][2] * g.alpha, v11 = c[i][j][3] * g.alpha;
            if (BIAS) {
                float b0 = g.bias[g.n0 + nc], b1 = g.bias[g.n0 + nc + 1];
                v00 += b0; v01 += b1; v10 += b0; v11 += b1;
            }
            if (OMODE == 0) {           // fp32 row-major
                float* Cf = (float*)g.C;
                *(float2*)(Cf + (size_t)r0 * g.ldc + g.n0 + nc)       = make_float2(v00, v01);
                *(float2*)(Cf + (size_t)(r0 + 8) * g.ldc + g.n0 + nc) = make_float2(v10, v11);
            } else if (OMODE == 1) {    // packed row-major
                uint32_t* Cu = (uint32_t*)g.C;
                *(uint2*)(Cu + (size_t)r0 * g.ldc + g.n0 + nc)       = make_uint2(pack_f32(v00), pack_f32(v01));
                *(uint2*)(Cu + (size_t)(r0 + 8) * g.ldc + g.n0 + nc) = make_uint2(pack_f32(v10), pack_f32(v11));
            } else {                    // packed transposed (Vt)
                uint32_t* Ct = (uint32_t*)g.C;
                const int bb0 = r0 / g.tr_rows, sr0 = r0 % g.tr_rows;
                const int bb1 = (r0 + 8) / g.tr_rows, sr1 = (r0 + 8) % g.tr_rows;
                const size_t base0 = (size_t)((bb0 * 4 + g.tr_col0) * 64 + nc) * g.tr_ld + sr0;
                const size_t base1 = (size_t)((bb1 * 4 + g.tr_col0) * 64 + nc) * g.tr_ld + sr1;
                Ct[base0]            = pack_f32(v00);
                Ct[base0 + g.tr_ld]  = pack_f32(v01);
                Ct[base1]            = pack_f32(v10);
                Ct[base1 + g.tr_ld]  = pack_f32(v11);
            }
        }
    }
#undef LOADR
#undef STS
#undef COMPUTE
}

// ---------------- kernel wrappers ----------------
__global__ void __launch_bounds__(256) k_proj_pack(const float* A, const float* W,
                                                   const float* bias, uint32_t* C) {
    GArgs g;
    g.A = (const uint32_t*)A; g.lda = Hd;
    g.B = (const uint32_t*)W; g.ldb = Hd;
    g.bias = bias; g.C = C; g.ldc = Hd; g.K = Hd; g.alpha = 1.f;
    g.m0 = blockIdx.y * 128; g.n0 = blockIdx.x * 64;
    g.tr_ld = 1; g.tr_rows = 1; g.tr_col0 = 0;
    gemm_mma<false, false, 1, true>(g);
}
__global__ void __launch_bounds__(256) k_proj_vt(const float* A, const float* W,
                                                 const float* bias, uint32_t* Vt, int Skv) {
    GArgs g;
    g.A = (const uint32_t*)A; g.lda = Hd;
    g.B = (const uint32_t*)W; g.ldb = Hd;
    g.bias = bias; g.C = Vt; g.ldc = Hd; g.K = Hd; g.alpha = 1.f;
    g.m0 = blockIdx.y * 128; g.n0 = blockIdx.x * 64;
    g.tr_ld = Skv; g.tr_rows = Skv; g.tr_col0 = blockIdx.x;
    gemm_mma<false, false, 2, true>(g);
}
__global__ void __launch_bounds__(256) k_proj_out(const uint32_t* A, const float* W,
                                                  const float* bias, float* C) {
    GArgs g;
    g.A = A; g.lda = Hd;
    g.B = (const uint32_t*)W; g.ldb = Hd;
    g.bias = bias; g.C = C; g.ldc = Hd; g.K = Hd; g.alpha = 1.f;
    g.m0 = blockIdx.y * 128; g.n0 = blockIdx.x * 64;
    g.tr_ld = 1; g.tr_rows = 1; g.tr_col0 = 0;
    gemm_mma<true, false, 0, true>(g);
}
__global__ void __launch_bounds__(256) k_scores_tc(const uint32_t* Q, const uint32_t* Kt,
                                                   float* So, int Sq, int Skv) {
    const int z = blockIdx.z, b = z >> 2, h = z & 3;
    GArgs g;
    g.A = Q + (size_t)b * Sq * Hd + h * HDd; g.lda = Hd;
    g.B = Kt + (size_t)b * Skv * Hd + h * HDd; g.ldb = Hd;
    g.bias = nullptr; g.C = So + (size_t)z * Sq * Skv; g.ldc = Skv;
    g.K = HDd; g.alpha = 2.0f;  // 1/TEMP
    g.m0 = blockIdx.y * 128; g.n0 = blockIdx.x * 64;
    g.tr_ld = 1; g.tr_rows = 1; g.tr_col0 = 0;
    gemm_mma<true, true, 0, false>(g);
}
__global__ void __launch_bounds__(256) k_pv_tc(const uint32_t* P, const uint32_t* Vt,
                                               uint32_t* attn, int Sq, int Skv) {
    const int z = blockIdx.z, b = z >> 2, h = z & 3;
    GArgs g;
    g.A = P + (size_t)z * Sq * Skv; g.lda = Skv;
    g.B = Vt + (size_t)z * HDd * Skv; g.ldb = Skv;
    g.bias = nullptr; g.C = attn + (size_t)b * Sq * Hd + h * HDd; g.ldc = Hd;
    g.K = Skv; g.alpha = 1.f;
    g.m0 = blockIdx.y * 128; g.n0 = 0;
    g.tr_ld = 1; g.tr_rows = 1; g.tr_col0 = 0;
    gemm_mma<true, true, 1, false>(g);
}

// ---------------- softmax: fp32 scores -> packed probs + head-avg A ----------------
__global__ void k_softmax(float* __restrict__ S, float* __restrict__ A, int Sq, int Skv) {
    extern __shared__ float sh[];            // [4][Skv]
    __shared__ float red[256];
    __shared__ float inv_sum[4], mx[4];
    const int q = blockIdx.x, b = blockIdx.y, t = threadIdx.x;

#pragma unroll
    for (int h = 0; h < 4; h++) {
        float* row = S + ((size_t)(b * 4 + h) * Sq + q) * (size_t)Skv;
        float lmax = -1e30f;
        for (int k = t; k < Skv; k += 256) {
            float v = row[k];
            sh[h * Skv + k] = v;
            lmax = fmaxf(lmax, v);
        }
        red[t] = lmax; __syncthreads();
        for (int s = 128; s > 0; s >>= 1) {
            if (t < s) red[t] = fmaxf(red[t], red[t + s]);
            __syncthreads();
        }
        if (t == 0) mx[h] = red[0];
        __syncthreads();
        const float m = mx[h];
        float lsum = 0.f;
        for (int k = t; k < Skv; k += 256) {
            float w = __expf(sh[h * Skv + k] - m);
            sh[h * Skv + k] = w;
            lsum += w;
        }
        red[t] = lsum; __syncthreads();
        for (int s = 128; s > 0; s >>= 1) {
            if (t < s) red[t] += red[t + s];
            __syncthreads();
        }
        if (t == 0) inv_sum[h] = 1.f / red[0];
        __syncthreads();
    }

    float* Arow = A + ((size_t)b * Sq + q) * (size_t)Skv;
    uint32_t* Su = (uint32_t*)S;
    for (int k = t; k < Skv; k += 256) {
        float a = 0.f;
#pragma unroll
        for (int h = 0; h < 4; h++) {
            float w = sh[h * Skv + k] * inv_sum[h];
            Su[((size_t)(b * 4 + h) * Sq + q) * (size_t)Skv + k] = pack_f32(w);
            a += w;
        }
        Arow[k] = 0.25f * a;
    }
}

// ---------------- relu + LayerNorm ----------------
__global__ void k_relu_ln(const float* __restrict__ O, const float* __restrict__ gamma,
                          const float* __restrict__ beta, float* __restrict__ out) {
    __shared__ float s1[256], s2[256];
    const int row = blockIdx.x, t = threadIdx.x;
    float x = O[(size_t)row * Hd + t];
    x = fmaxf(x, 0.f);
    s1[t] = x; s2[t] = x * x;
    __syncthreads();
    for (int s = 128; s > 0; s >>= 1) {
        if (t < s) { s1[t] += s1[t + s]; s2[t] += s2[t + s]; }
        __syncthreads();
    }
    const float mean = s1[0] * (1.f / Hd);
    const float var = s2[0] * (1.f / Hd) - mean * mean;
    const float rstd = rsqrtf(var + 1e-5f);
    out[(size_t)row * Hd + t] = (x - mean) * rstd * gamma[t] + beta[t];
}

// ---------------- launch ----------------
extern "C" void kernel_launch(void* const* d_in, const int* in_sizes, int n_in,
                              void* d_out, int out_size) {
    const float* image  = (const float*)d_in[0];
    const float* text   = (const float*)d_in[1];
    const float* i2t_wq = (const float*)d_in[2];
    const float* i2t_bq = (const float*)d_in[3];
    const float* i2t_wk = (const float*)d_in[4];
    const float* i2t_bk = (const float*)d_in[5];
    const float* i2t_wv = (const float*)d_in[6];
    const float* i2t_bv = (const float*)d_in[7];
    const float* i2t_wo = (const float*)d_in[8];
    const float* i2t_bo = (const float*)d_in[9];
    const float* i2t_g  = (const float*)d_in[10];
    const float* i2t_be = (const float*)d_in[11];
    const float* t2i_wq = (const float*)d_in[12];
    const float* t2i_bq = (const float*)d_in[13];
    const float* t2i_wk = (const float*)d_in[14];
    const float* t2i_bk = (const float*)d_in[15];
    const float* t2i_wv = (const float*)d_in[16];
    const float* t2i_bv = (const float*)d_in[17];
    const float* t2i_wo = (const float*)d_in[18];
    const float* t2i_bo = (const float*)d_in[19];
    const float* t2i_g  = (const float*)d_in[20];
    const float* t2i_be = (const float*)d_in[21];

    float* out = (float*)d_out;
    float* out_i2t_feat = out;
    float* out_t2i_feat = out + (size_t)RI * Hd;
    float* out_i2t_A    = out_t2i_feat + (size_t)RT * Hd;
    float* out_t2i_A    = out_i2t_A + (size_t)BAT * SQI * SQT;

    float *qi, *ki, *vi, *qt, *kt, *vt, *ai, *at, *oi, *ot, *S;
    cudaGetSymbolAddress((void**)&qi, g_qi);
    cudaGetSymbolAddress((void**)&ki, g_ki);
    cudaGetSymbolAddress((void**)&vi, g_vi);
    cudaGetSymbolAddress((void**)&qt, g_qt);
    cudaGetSymbolAddress((void**)&kt, g_kt);
    cudaGetSymbolAddress((void**)&vt, g_vt);
    cudaGetSymbolAddress((void**)&ai, g_ai);
    cudaGetSymbolAddress((void**)&at, g_at);
    cudaGetSymbolAddress((void**)&oi, g_oi);
    cudaGetSymbolAddress((void**)&ot, g_ot);
    cudaGetSymbolAddress((void**)&S,  g_S);

    cudaFuncSetAttribute(k_proj_pack, cudaFuncAttributeMaxDynamicSharedMemorySize, SMEM_GEMM);
    cudaFuncSetAttribute(k_proj_vt,   cudaFuncAttributeMaxDynamicSharedMemorySize, SMEM_GEMM);
    cudaFuncSetAttribute(k_proj_out,  cudaFuncAttributeMaxDynamicSharedMemorySize, SMEM_GEMM);
    cudaFuncSetAttribute(k_scores_tc, cudaFuncAttributeMaxDynamicSharedMemorySize, SMEM_GEMM);
    cudaFuncSetAttribute(k_pv_tc,     cudaFuncAttributeMaxDynamicSharedMemorySize, SMEM_GEMM);

    const dim3 blk(256);

    // ---- projections ----
    k_proj_pack<<<dim3(4, RI / 128), blk, SMEM_GEMM>>>(image, i2t_wq, i2t_bq, (uint32_t*)qi);
    k_proj_pack<<<dim3(4, RT / 128), blk, SMEM_GEMM>>>(text, i2t_wk, i2t_bk, (uint32_t*)kt);
    k_proj_vt  <<<dim3(4, RT / 128), blk, SMEM_GEMM>>>(text, i2t_wv, i2t_bv, (uint32_t*)vt, SQT);
    k_proj_pack<<<dim3(4, RT / 128), blk, SMEM_GEMM>>>(text, t2i_wq, t2i_bq, (uint32_t*)qt);
    k_proj_pack<<<dim3(4, RI / 128), blk, SMEM_GEMM>>>(image, t2i_wk, t2i_bk, (uint32_t*)ki);
    k_proj_vt  <<<dim3(4, RI / 128), blk, SMEM_GEMM>>>(image, t2i_wv, t2i_bv, (uint32_t*)vi, SQI);

    // ---- i2t ----
    k_scores_tc<<<dim3(SQT / 64, SQI / 128, BAT * NHd), blk, SMEM_GEMM>>>(
        (const uint32_t*)qi, (const uint32_t*)kt, S, SQI, SQT);
    k_softmax<<<dim3(SQI, BAT), blk, 4 * SQT * sizeof(float)>>>(S, out_i2t_A, SQI, SQT);
    k_pv_tc<<<dim3(1, SQI / 128, BAT * NHd), blk, SMEM_GEMM>>>(
        (const uint32_t*)S, (const uint32_t*)vt, (uint32_t*)ai, SQI, SQT);
    k_proj_out<<<dim3(4, RI / 128), blk, SMEM_GEMM>>>((const uint32_t*)ai, i2t_wo, i2t_bo, oi);
    k_relu_ln<<<RI, blk>>>(oi, i2t_g, i2t_be, out_i2t_feat);

    // ---- t2i ----
    k_scores_tc<<<dim3(SQI / 64, SQT / 128, BAT * NHd), blk, SMEM_GEMM>>>(
        (const uint32_t*)qt, (const uint32_t*)ki, S, SQT, SQI);
    k_softmax<<<dim3(SQT, BAT), blk, 4 * SQI * sizeof(float)>>>(S, out_t2i_A, SQT, SQI);
    k_pv_tc<<<dim3(1, SQT / 128, BAT * NHd), blk, SMEM_GEMM>>>(
        (const uint32_t*)S, (const uint32_t*)vi, (uint32_t*)at, SQT, SQI);
    k_proj_out<<<dim3(4, RT / 128), blk, SMEM_GEMM>>>((const uint32_t*)at, t2i_wo, t2i_bo, ot);
    k_relu_ln<<<RT, blk>>>(ot, t2i_g, t2i_be, out_t2i_feat);
}

// round 9
// speedup vs baseline: 1.9645x; 1.1996x over previous
#include <cuda_runtime.h>
#include <cuda_bf16.h>
#include <cstdint>
#include <math.h>

// ---------------- problem constants ----------------
#define Hd   256
#define NHd  4
#define HDd  64
#define BAT  8
#define SQI  2048
#define SQT  1024
#define RI   (BAT*SQI)       // 16384 image rows
#define RT   (BAT*SQT)       // 8192 text rows
#define NRS  (RI*NHd/4 + RT*NHd/4)   // rowsum entries: 65536 + 32768

// ---------------- scratch ----------------
__device__ float g_qi[(size_t)RI*Hd];   // packed hi/lo bf16 pairs
__device__ float g_ki[(size_t)RI*Hd];
__device__ float g_vi[(size_t)RI*Hd];   // packed, TRANSPOSED [B*4+hgrp][64][SQI]
__device__ float g_qt[(size_t)RT*Hd];
__device__ float g_kt[(size_t)RT*Hd];
__device__ float g_vt[(size_t)RT*Hd];   // packed, TRANSPOSED
__device__ float g_ai[(size_t)RI*Hd];   // packed attn (pre O-proj)
__device__ float g_at[(size_t)RT*Hd];
__device__ float g_oi[(size_t)RI*Hd];   // fp32 O-proj out
__device__ float g_ot[(size_t)RT*Hd];
__device__ float g_S[(size_t)BAT*NHd*SQI*SQT]; // packed exp(scores) (w values)
__device__ float g_rsum[NRS];           // per-row sums of w (i2t first, then t2i)

// ================= helpers =================
__device__ __forceinline__ uint32_t smem_to_u32(const void* p) {
    uint32_t a;
    asm("{ .reg .u64 t; cvta.to.shared.u64 t, %1; cvt.u32.u64 %0, t; }" : "=r"(a) : "l"(p));
    return a;
}
__device__ __forceinline__ void ldm_x4(uint32_t r[4], uint32_t addr) {
    asm volatile("ldmatrix.sync.aligned.m8n8.x4.shared.b16 {%0,%1,%2,%3}, [%4];"
        : "=r"(r[0]), "=r"(r[1]), "=r"(r[2]), "=r"(r[3]) : "r"(addr));
}
__device__ __forceinline__ void mma_bf16(float c[4], const uint32_t a[4],
                                         uint32_t b0, uint32_t b1) {
    asm volatile(
        "mma.sync.aligned.m16n8k16.row.col.f32.bf16.bf16.f32 "
        "{%0,%1,%2,%3}, {%4,%5,%6,%7}, {%8,%9}, {%0,%1,%2,%3};"
        : "+f"(c[0]), "+f"(c[1]), "+f"(c[2]), "+f"(c[3])
        : "r"(a[0]), "r"(a[1]), "r"(a[2]), "r"(a[3]), "r"(b0), "r"(b1));
}

__device__ __forceinline__ void split_f32(uint32_t u, uint32_t& h, uint32_t& l) {
    float x = __uint_as_float(u);
    __nv_bfloat16 hb = __float2bfloat16(x);
    float hf = __bfloat162float(hb);
    __nv_bfloat16 lb = __float2bfloat16(x - hf);
    h = (uint32_t)__bfloat16_as_ushort(hb);
    l = (uint32_t)__bfloat16_as_ushort(lb);
}
__device__ __forceinline__ uint32_t pack_f32(float x) {
    __nv_bfloat16 hb = __float2bfloat16(x);
    float hf = __bfloat162float(hb);
    __nv_bfloat16 lb = __float2bfloat16(x - hf);
    return ((uint32_t)__bfloat16_as_ushort(hb) << 16) | (uint32_t)__bfloat16_as_ushort(lb);
}
__device__ __forceinline__ float unpack_f32(uint32_t u) {
    return __bfloat162float(__ushort_as_bfloat16((unsigned short)(u >> 16)))
         + __bfloat162float(__ushort_as_bfloat16((unsigned short)(u & 0xffff)));
}

// ---------------- smem layout ----------------
// per stage: Ah[128][40]bf16 (10240B), Al (10240B), Bh[64][40] (5120B), Bl (5120B)
#define STG_BYTES 30720
#define OFF_AL 10240
#define OFF_BH 20480
#define OFF_BL 25600
#define SMEM_GEMM (2*STG_BYTES)   // 61440

struct GArgs {
    const uint32_t* A; int lda;
    const uint32_t* B; int ldb;
    const float* bias;
    void* C; int ldc;
    int K; float alpha;
    int m0, n0;
    int tr_ld, tr_rows, tr_col0;
    const float* rs;      // OMODE1: per-row scale (1/rs), or nullptr
};

template <bool PACKED>
__device__ __forceinline__ void sts4(uint16_t* hi, uint16_t* lo, int idx, uint4 v) {
    uint32_t h0, h1, h2, h3, l0, l1, l2, l3;
    if (PACKED) {
        h0 = v.x >> 16; l0 = v.x & 0xffff;
        h1 = v.y >> 16; l1 = v.y & 0xffff;
        h2 = v.z >> 16; l2 = v.z & 0xffff;
        h3 = v.w >> 16; l3 = v.w & 0xffff;
    } else {
        split_f32(v.x, h0, l0); split_f32(v.y, h1, l1);
        split_f32(v.z, h2, l2); split_f32(v.w, h3, l3);
    }
    *(uint32_t*)(hi + idx)     = h0 | (h1 << 16);
    *(uint32_t*)(hi + idx + 2) = h2 | (h3 << 16);
    *(uint32_t*)(lo + idx)     = l0 | (l1 << 16);
    *(uint32_t*)(lo + idx + 2) = l2 | (l3 << 16);
}

// OMODE: 0 = fp32 row-major, 1 = packed row-major (optional rowsum scale),
//        2 = packed transposed (Vt), 3 = packed exp (scores -> w)
template <bool APACK, bool BPACK, int OMODE, bool BIAS>
__device__ void gemm_mma(GArgs g) {
    extern __shared__ char smem[];
    const uint32_t sbase = smem_to_u32(smem);
    const int tid = threadIdx.x;
    const int lane = tid & 31, wid = tid >> 5;
    const int warpM = wid >> 1, warpN = wid & 1;     // 4 x 2 warps

    float c[2][4][4];
#pragma unroll
    for (int i = 0; i < 2; i++)
#pragma unroll
        for (int j = 0; j < 4; j++)
#pragma unroll
            for (int q = 0; q < 4; q++) c[i][j][q] = 0.f;

    const int S = g.K >> 5;                    // K-chunks of 32
    const int arow = tid >> 1, ak0 = (tid & 1) * 16;
    const int brow = tid >> 2, bk0 = (tid & 3) * 8;

    uint4 areg[4], breg[2];

#define LOADR(s) do { \
        const uint32_t* Ap = g.A + (size_t)(g.m0 + arow) * g.lda + (s) * 32 + ak0; \
        _Pragma("unroll") for (int j = 0; j < 4; j++) areg[j] = *(const uint4*)(Ap + j * 4); \
        const uint32_t* Bp = g.B + (size_t)(g.n0 + brow) * g.ldb + (s) * 32 + bk0; \
        _Pragma("unroll") for (int j = 0; j < 2; j++) breg[j] = *(const uint4*)(Bp + j * 4); \
    } while (0)

#define STS(buf) do { \
        char* p = smem + (buf) * STG_BYTES; \
        uint16_t* Ah = (uint16_t*)p;               uint16_t* Al = (uint16_t*)(p + OFF_AL); \
        uint16_t* Bh = (uint16_t*)(p + OFF_BH);    uint16_t* Bl = (uint16_t*)(p + OFF_BL); \
        _Pragma("unroll") for (int j = 0; j < 4; j++) \
            sts4<APACK>(Ah, Al, arow * 40 + ak0 + j * 4, areg[j]); \
        _Pragma("unroll") for (int j = 0; j < 2; j++) \
            sts4<BPACK>(Bh, Bl, brow * 40 + bk0 + j * 4, breg[j]); \
    } while (0)

    const int sel = lane >> 3, r8 = lane & 7;
    const int rloc = (sel & 1) * 8 + r8;     // row within 16-row tile
    const int cloc = (sel >> 1) * 8;         // col(halves) within 16-k tile

#define COMPUTE(buf) do { \
        uint32_t AhB = sbase + (buf) * STG_BYTES, AlB = AhB + OFF_AL; \
        uint32_t BhB = AhB + OFF_BH,              BlB = AhB + OFF_BL; \
        _Pragma("unroll") for (int kh = 0; kh < 2; kh++) { \
            uint32_t ah[2][4], al[2][4], bh[2][4], bl[2][4]; \
            _Pragma("unroll") for (int i = 0; i < 2; i++) { \
                uint32_t off = (uint32_t)(((warpM * 32 + i * 16 + rloc) * 40 + kh * 16 + cloc) * 2); \
                ldm_x4(ah[i], AhB + off); ldm_x4(al[i], AlB + off); \
            } \
            _Pragma("unroll") for (int pp = 0; pp < 2; pp++) { \
                uint32_t off = (uint32_t)(((warpN * 32 + pp * 16 + rloc) * 40 + kh * 16 + cloc) * 2); \
                ldm_x4(bh[pp], BhB + off); ldm_x4(bl[pp], BlB + off); \
            } \
            _Pragma("unroll") for (int i = 0; i < 2; i++) \
            _Pragma("unroll") for (int j = 0; j < 4; j++) { \
                const int pp = j >> 1, q = j & 1; \
                mma_bf16(c[i][j], ah[i], bh[pp][q], bh[pp][q + 2]); \
                mma_bf16(c[i][j], ah[i], bl[pp][q], bl[pp][q + 2]); \
                mma_bf16(c[i][j], al[i], bh[pp][q], bh[pp][q + 2]); \
            } \
        } \
    } while (0)

    LOADR(0); STS(0);
    __syncthreads();
    // next-stage LDGs issue first, compute current, then store — LDG latency
    // hides under the 48-MMA compute body. Buffers s&1 vs (s+1)&1 are disjoint.
    for (int s = 0; s < S; ++s) {
        if (s + 1 < S) LOADR(s + 1);
        COMPUTE(s & 1);
        if (s + 1 < S) STS((s + 1) & 1);
        __syncthreads();
    }

    // ---------------- epilogue ----------------
    const int gq = lane >> 2, tig = lane & 3;
#pragma unroll
    for (int i = 0; i < 2; i++) {
        const int r0 = g.m0 + warpM * 32 + i * 16 + gq;   // and r0+8
        float inv0 = 1.f, inv1 = 1.f;
        if (OMODE == 1) {
            if (g.rs) { inv0 = 1.f / g.rs[r0]; inv1 = 1.f / g.rs[r0 + 8]; }
        }
#pragma unroll
        for (int j = 0; j < 4; j++) {
            const int nc = warpN * 32 + j * 8 + tig * 2;   // local col (0..63)
            float v00 = c[i][j][0] * g.alpha, v01 = c[i][j][1] * g.alpha;
            float v10 = c[i][j][2] * g.alpha, v11 = c[i][j][3] * g.alpha;
            if (BIAS) {
                float b0 = g.bias[g.n0 + nc], b1 = g.bias[g.n0 + nc + 1];
                v00 += b0; v01 += b1; v10 += b0; v11 += b1;
            }
            if (OMODE == 0) {           // fp32 row-major
                float* Cf = (float*)g.C;
                *(float2*)(Cf + (size_t)r0 * g.ldc + g.n0 + nc)       = make_float2(v00, v01);
                *(float2*)(Cf + (size_t)(r0 + 8) * g.ldc + g.n0 + nc) = make_float2(v10, v11);
            } else if (OMODE == 1) {    // packed row-major (opt. row scale)
                v00 *= inv0; v01 *= inv0; v10 *= inv1; v11 *= inv1;
                uint32_t* Cu = (uint32_t*)g.C;
                *(uint2*)(Cu + (size_t)r0 * g.ldc + g.n0 + nc)       = make_uint2(pack_f32(v00), pack_f32(v01));
                *(uint2*)(Cu + (size_t)(r0 + 8) * g.ldc + g.n0 + nc) = make_uint2(pack_f32(v10), pack_f32(v11));
            } else if (OMODE == 2) {    // packed transposed (Vt)
                uint32_t* Ct = (uint32_t*)g.C;
                const int bb0 = r0 / g.tr_rows, sr0 = r0 % g.tr_rows;
                const int bb1 = (r0 + 8) / g.tr_rows, sr1 = (r0 + 8) % g.tr_rows;
                const size_t base0 = (size_t)((bb0 * 4 + g.tr_col0) * 64 + nc) * g.tr_ld + sr0;
                const size_t base1 = (size_t)((bb1 * 4 + g.tr_col0) * 64 + nc) * g.tr_ld + sr1;
                Ct[base0]            = pack_f32(v00);
                Ct[base0 + g.tr_ld]  = pack_f32(v01);
                Ct[base1]            = pack_f32(v10);
                Ct[base1 + g.tr_ld]  = pack_f32(v11);
            } else {                    // OMODE 3: packed exp(score)
                uint32_t* Cu = (uint32_t*)g.C;
                *(uint2*)(Cu + (size_t)r0 * g.ldc + g.n0 + nc) =
                    make_uint2(pack_f32(__expf(v00)), pack_f32(__expf(v01)));
                *(uint2*)(Cu + (size_t)(r0 + 8) * g.ldc + g.n0 + nc) =
                    make_uint2(pack_f32(__expf(v10)), pack_f32(__expf(v11)));
            }
        }
    }
#undef LOADR
#undef STS
#undef COMPUTE
}

// ---------------- kernel wrappers ----------------
__global__ void __launch_bounds__(256) k_proj_pack(const float* A, const float* W,
                                                   const float* bias, uint32_t* C) {
    GArgs g;
    g.A = (const uint32_t*)A; g.lda = Hd;
    g.B = (const uint32_t*)W; g.ldb = Hd;
    g.bias = bias; g.C = C; g.ldc = Hd; g.K = Hd; g.alpha = 1.f;
    g.m0 = blockIdx.y * 128; g.n0 = blockIdx.x * 64;
    g.tr_ld = 1; g.tr_rows = 1; g.tr_col0 = 0; g.rs = nullptr;
    gemm_mma<false, false, 1, true>(g);
}
__global__ void __launch_bounds__(256) k_proj_vt(const float* A, const float* W,
                                                 const float* bias, uint32_t* Vt, int Skv) {
    GArgs g;
    g.A = (const uint32_t*)A; g.lda = Hd;
    g.B = (const uint32_t*)W; g.ldb = Hd;
    g.bias = bias; g.C = Vt; g.ldc = Hd; g.K = Hd; g.alpha = 1.f;
    g.m0 = blockIdx.y * 128; g.n0 = blockIdx.x * 64;
    g.tr_ld = Skv; g.tr_rows = Skv; g.tr_col0 = blockIdx.x; g.rs = nullptr;
    gemm_mma<false, false, 2, true>(g);
}
__global__ void __launch_bounds__(256) k_proj_out(const uint32_t* A, const float* W,
                                                  const float* bias, float* C) {
    GArgs g;
    g.A = A; g.lda = Hd;
    g.B = (const uint32_t*)W; g.ldb = Hd;
    g.bias = bias; g.C = C; g.ldc = Hd; g.K = Hd; g.alpha = 1.f;
    g.m0 = blockIdx.y * 128; g.n0 = blockIdx.x * 64;
    g.tr_ld = 1; g.tr_rows = 1; g.tr_col0 = 0; g.rs = nullptr;
    gemm_mma<true, false, 0, true>(g);
}
// scores -> w = exp(2*q.k), packed (no normalization here)
__global__ void __launch_bounds__(256) k_scores_tc(const uint32_t* Q, const uint32_t* Kt,
                                                   uint32_t* So, int Sq, int Skv) {
    const int z = blockIdx.z, b = z >> 2, h = z & 3;
    GArgs g;
    g.A = Q + (size_t)b * Sq * Hd + h * HDd; g.lda = Hd;
    g.B = Kt + (size_t)b * Skv * Hd + h * HDd; g.ldb = Hd;
    g.bias = nullptr; g.C = So + (size_t)z * Sq * Skv; g.ldc = Skv;
    g.K = HDd; g.alpha = 2.0f;  // 1/TEMP
    g.m0 = blockIdx.y * 128; g.n0 = blockIdx.x * 64;
    g.tr_ld = 1; g.tr_rows = 1; g.tr_col0 = 0; g.rs = nullptr;
    gemm_mma<true, true, 3, false>(g);
}
// P@V with epilogue row scaling by 1/rowsum
__global__ void __launch_bounds__(256) k_pv_tc(const uint32_t* P, const uint32_t* Vt,
                                               uint32_t* attn, const float* rsum, int Sq, int Skv) {
    const int z = blockIdx.z, b = z >> 2, h = z & 3;
    GArgs g;
    g.A = P + (size_t)z * Sq * Skv; g.lda = Skv;
    g.B = Vt + (size_t)z * HDd * Skv; g.ldb = Skv;
    g.bias = nullptr; g.C = attn + (size_t)b * Sq * Hd + h * HDd; g.ldc = Hd;
    g.K = Skv; g.alpha = 1.f;
    g.m0 = blockIdx.y * 128; g.n0 = 0;
    g.tr_ld = 1; g.tr_rows = 1; g.tr_col0 = 0;
    g.rs = rsum + (size_t)z * Sq;
    gemm_mma<true, true, 1, false>(g);
}

// ---------------- rowsums + head-averaged A (deterministic, no atomics) ----------------
// grid (Sq, B), block 256, dyn smem 4*Skv*4 bytes. Writes rs for PV and A output.
__global__ void k_sumavg(const uint32_t* __restrict__ W, float* __restrict__ rs,
                         float* __restrict__ A, int Sq, int Skv) {
    extern __shared__ float sh[];            // [4][Skv]
    __shared__ float red[256];
    __shared__ float inv[4];
    const int q = blockIdx.x, b = blockIdx.y, t = threadIdx.x;
    const size_t hstride = (size_t)Sq * Skv;
    const uint32_t* w0 = W + ((size_t)(b * 4) * Sq + q) * (size_t)Skv;

#pragma unroll
    for (int h = 0; h < 4; h++) {
        float lsum = 0.f;
        for (int k = t; k < Skv; k += 256) {
            float w = unpack_f32(w0[(size_t)h * hstride + k]);
            sh[h * Skv + k] = w;
            lsum += w;
        }
        red[t] = lsum; __syncthreads();
        for (int s = 128; s > 0; s >>= 1) {
            if (t < s) red[t] += red[t + s];
            __syncthreads();
        }
        if (t == 0) {
            rs[(size_t)(b * 4 + h) * Sq + q] = red[0];
            inv[h] = 0.25f / red[0];
        }
        __syncthreads();
    }

    float* Ar = A + ((size_t)b * Sq + q) * (size_t)Skv;
    for (int k = t; k < Skv; k += 256) {
        float a = 0.f;
#pragma unroll
        for (int h = 0; h < 4; h++)
            a += sh[h * Skv + k] * inv[h];
        Ar[k] = a;
    }
}

// ---------------- relu + LayerNorm ----------------
__global__ void k_relu_ln(const float* __restrict__ O, const float* __restrict__ gamma,
                          const float* __restrict__ beta, float* __restrict__ out) {
    __shared__ float s1[256], s2[256];
    const int row = blockIdx.x, t = threadIdx.x;
    float x = O[(size_t)row * Hd + t];
    x = fmaxf(x, 0.f);
    s1[t] = x; s2[t] = x * x;
    __syncthreads();
    for (int s = 128; s > 0; s >>= 1) {
        if (t < s) { s1[t] += s1[t + s]; s2[t] += s2[t + s]; }
        __syncthreads();
    }
    const float mean = s1[0] * (1.f / Hd);
    const float var = s2[0] * (1.f / Hd) - mean * mean;
    const float rstd = rsqrtf(var + 1e-5f);
    out[(size_t)row * Hd + t] = (x - mean) * rstd * gamma[t] + beta[t];
}

// ---------------- launch ----------------
extern "C" void kernel_launch(void* const* d_in, const int* in_sizes, int n_in,
                              void* d_out, int out_size) {
    const float* image  = (const float*)d_in[0];
    const float* text   = (const float*)d_in[1];
    const float* i2t_wq = (const float*)d_in[2];
    const float* i2t_bq = (const float*)d_in[3];
    const float* i2t_wk = (const float*)d_in[4];
    const float* i2t_bk = (const float*)d_in[5];
    const float* i2t_wv = (const float*)d_in[6];
    const float* i2t_bv = (const float*)d_in[7];
    const float* i2t_wo = (const float*)d_in[8];
    const float* i2t_bo = (const float*)d_in[9];
    const float* i2t_g  = (const float*)d_in[10];
    const float* i2t_be = (const float*)d_in[11];
    const float* t2i_wq = (const float*)d_in[12];
    const float* t2i_bq = (const float*)d_in[13];
    const float* t2i_wk = (const float*)d_in[14];
    const float* t2i_bk = (const float*)d_in[15];
    const float* t2i_wv = (const float*)d_in[16];
    const float* t2i_bv = (const float*)d_in[17];
    const float* t2i_wo = (const float*)d_in[18];
    const float* t2i_bo = (const float*)d_in[19];
    const float* t2i_g  = (const float*)d_in[20];
    const float* t2i_be = (const float*)d_in[21];

    float* out = (float*)d_out;
    float* out_i2t_feat = out;
    float* out_t2i_feat = out + (size_t)RI * Hd;
    float* out_i2t_A    = out_t2i_feat + (size_t)RT * Hd;
    float* out_t2i_A    = out_i2t_A + (size_t)BAT * SQI * SQT;

    float *qi, *ki, *vi, *qt, *kt, *vt, *ai, *at, *oi, *ot, *S, *rsum;
    cudaGetSymbolAddress((void**)&qi, g_qi);
    cudaGetSymbolAddress((void**)&ki, g_ki);
    cudaGetSymbolAddress((void**)&vi, g_vi);
    cudaGetSymbolAddress((void**)&qt, g_qt);
    cudaGetSymbolAddress((void**)&kt, g_kt);
    cudaGetSymbolAddress((void**)&vt, g_vt);
    cudaGetSymbolAddress((void**)&ai, g_ai);
    cudaGetSymbolAddress((void**)&at, g_at);
    cudaGetSymbolAddress((void**)&oi, g_oi);
    cudaGetSymbolAddress((void**)&ot, g_ot);
    cudaGetSymbolAddress((void**)&S,  g_S);
    cudaGetSymbolAddress((void**)&rsum, g_rsum);
    float* rsA = rsum;                            // i2t: 8*4*2048
    float* rsB = rsum + (size_t)BAT * NHd * SQI;  // t2i: 8*4*1024

    cudaFuncSetAttribute(k_proj_pack, cudaFuncAttributeMaxDynamicSharedMemorySize, SMEM_GEMM);
    cudaFuncSetAttribute(k_proj_vt,   cudaFuncAttributeMaxDynamicSharedMemorySize, SMEM_GEMM);
    cudaFuncSetAttribute(k_proj_out,  cudaFuncAttributeMaxDynamicSharedMemorySize, SMEM_GEMM);
    cudaFuncSetAttribute(k_scores_tc, cudaFuncAttributeMaxDynamicSharedMemorySize, SMEM_GEMM);
    cudaFuncSetAttribute(k_pv_tc,     cudaFuncAttributeMaxDynamicSharedMemorySize, SMEM_GEMM);

    const dim3 blk(256);

    // ---- projections ----
    k_proj_pack<<<dim3(4, RI / 128), blk, SMEM_GEMM>>>(image, i2t_wq, i2t_bq, (uint32_t*)qi);
    k_proj_pack<<<dim3(4, RT / 128), blk, SMEM_GEMM>>>(text, i2t_wk, i2t_bk, (uint32_t*)kt);
    k_proj_vt  <<<dim3(4, RT / 128), blk, SMEM_GEMM>>>(text, i2t_wv, i2t_bv, (uint32_t*)vt, SQT);
    k_proj_pack<<<dim3(4, RT / 128), blk, SMEM_GEMM>>>(text, t2i_wq, t2i_bq, (uint32_t*)qt);
    k_proj_pack<<<dim3(4, RI / 128), blk, SMEM_GEMM>>>(image, t2i_wk, t2i_bk, (uint32_t*)ki);
    k_proj_vt  <<<dim3(4, RI / 128), blk, SMEM_GEMM>>>(image, t2i_wv, t2i_bv, (uint32_t*)vi, SQI);

    // ---- i2t ----
    k_scores_tc<<<dim3(SQT / 64, SQI / 128, BAT * NHd), blk, SMEM_GEMM>>>(
        (const uint32_t*)qi, (const uint32_t*)kt, (uint32_t*)S, SQI, SQT);
    k_sumavg<<<dim3(SQI, BAT), blk, 4 * SQT * sizeof(float)>>>(
        (const uint32_t*)S, rsA, out_i2t_A, SQI, SQT);
    k_pv_tc<<<dim3(1, SQI / 128, BAT * NHd), blk, SMEM_GEMM>>>(
        (const uint32_t*)S, (const uint32_t*)vt, (uint32_t*)ai, rsA, SQI, SQT);
    k_proj_out<<<dim3(4, RI / 128), blk, SMEM_GEMM>>>((const uint32_t*)ai, i2t_wo, i2t_bo, oi);
    k_relu_ln<<<RI, blk>>>(oi, i2t_g, i2t_be, out_i2t_feat);

    // ---- t2i ----
    k_scores_tc<<<dim3(SQI / 64, SQT / 128, BAT * NHd), blk, SMEM_GEMM>>>(
        (const uint32_t*)qt, (const uint32_t*)ki, (uint32_t*)S, SQT, SQI);
    k_sumavg<<<dim3(SQT, BAT), blk, 4 * SQI * sizeof(float)>>>(
        (const uint32_t*)S, rsB, out_t2i_A, SQT, SQI);
    k_pv_tc<<<dim3(1, SQT / 128, BAT * NHd), blk, SMEM_GEMM>>>(
        (const uint32_t*)S, (const uint32_t*)vi, (uint32_t*)at, rsB, SQT, SQI);
    k_proj_out<<<dim3(4, RT / 128), blk, SMEM_GEMM>>>((const uint32_t*)at, t2i_wo, t2i_bo, ot);
    k_relu_ln<<<RT, blk>>>(ot, t2i_g, t2i_be, out_t2i_feat);
}